// round 1
// baseline (speedup 1.0000x reference)
#include <cuda_runtime.h>
#include <math.h>

#define E 8
#define D 1024
#define H 4096
#define O 1024
#define NTOK 4096
#define TOPK 2

// ---------------- scratch (static device globals; no allocs allowed) ----------------
__device__ int   d_counts[E];
__device__ int   d_offs[E];
__device__ int   d_tok[E * NTOK];      // padded per-expert token lists
__device__ float d_wt[E * NTOK];       // routing weight per entry
__device__ int   d_slot[NTOK * TOPK];  // padded index e*NTOK+pos per (token,k)
__device__ float d_h[(size_t)(NTOK * TOPK) * H];  // 8192*4096 f32 = 128 MB
__device__ float d_y[(size_t)(NTOK * TOPK) * O];  // 8192*1024 f32 = 32 MB

// ---------------- routing ----------------
__global__ void zero_counts_kernel() {
    if (threadIdx.x < E) d_counts[threadIdx.x] = 0;
}

__global__ void gate_kernel(const float* __restrict__ x,
                            const float* __restrict__ Wg,
                            const float* __restrict__ bg) {
    int n = blockIdx.x;
    int tid = threadIdx.x;
    int w = tid >> 5;          // warp = expert (8 warps)
    int lane = tid & 31;
    const float* xr = x + (size_t)n * D;

    float acc = 0.f;
    for (int d = lane; d < D; d += 32)
        acc += xr[d] * Wg[d * E + w];
    #pragma unroll
    for (int off = 16; off; off >>= 1)
        acc += __shfl_down_sync(0xffffffffu, acc, off);

    __shared__ float logits[E];
    if (lane == 0) logits[w] = acc + bg[w];
    __syncthreads();

    if (tid == 0) {
        int i0 = 0; float v0 = logits[0];
        #pragma unroll
        for (int e = 1; e < E; e++)
            if (logits[e] > v0) { v0 = logits[e]; i0 = e; }
        int i1 = -1; float v1 = -3.0e38f;
        #pragma unroll
        for (int e = 0; e < E; e++)
            if (e != i0 && logits[e] > v1) { v1 = logits[e]; i1 = e; }
        // softmax over (v0 >= v1)
        float w0 = 1.f / (1.f + expf(v1 - v0));
        float w1 = 1.f - w0;

        int p0 = atomicAdd(&d_counts[i0], 1);
        d_tok[i0 * NTOK + p0] = n;
        d_wt [i0 * NTOK + p0] = w0;
        d_slot[n * 2 + 0] = i0 * NTOK + p0;

        int p1 = atomicAdd(&d_counts[i1], 1);
        d_tok[i1 * NTOK + p1] = n;
        d_wt [i1 * NTOK + p1] = w1;
        d_slot[n * 2 + 1] = i1 * NTOK + p1;
    }
}

__global__ void scan_kernel() {
    if (threadIdx.x == 0) {
        int t = 0;
        #pragma unroll
        for (int e = 0; e < E; e++) { d_offs[e] = t; t += d_counts[e]; }
    }
}

// ---------------- grouped GEMM 1: h = relu(Xg @ W1[e] + b1[e]) ----------------
// tiles: 64(M) x 64(N) x 16(K), 256 threads, 4x4 register micro-tile
__global__ __launch_bounds__(256) void gemm1_kernel(const float* __restrict__ x,
                                                    const float* __restrict__ W1,
                                                    const float* __restrict__ b1) {
    const int e = blockIdx.z;
    const int C = d_counts[e];
    const int m0 = blockIdx.y * 64;
    if (m0 >= C) return;
    const int n0 = blockIdx.x * 64;

    __shared__ __align__(16) float As[16][64];
    __shared__ __align__(16) float Bs[16][64];

    const int tid = threadIdx.x;
    const int a_row = tid >> 2;          // 0..63 (m)
    const int a_col = (tid & 3) << 2;    // 0,4,8,12 (k)
    const int b_row = tid >> 4;          // 0..15 (k)
    const int b_col = (tid & 15) << 2;   // 0..60 (n)
    const int ty = tid >> 4;             // 0..15
    const int tx = tid & 15;             // 0..15

    int mi = m0 + a_row;
    int tok = d_tok[e * NTOK + (mi < C ? mi : 0)];
    const float* arow = x + (size_t)tok * D;
    const float* bptr = W1 + (size_t)e * D * H + n0;

    float acc[4][4] = {};

    for (int k0 = 0; k0 < D; k0 += 16) {
        float4 av = *(const float4*)(arow + k0 + a_col);
        float4 bv = *(const float4*)(bptr + (size_t)(k0 + b_row) * H + b_col);
        As[a_col + 0][a_row] = av.x;
        As[a_col + 1][a_row] = av.y;
        As[a_col + 2][a_row] = av.z;
        As[a_col + 3][a_row] = av.w;
        *(float4*)&Bs[b_row][b_col] = bv;
        __syncthreads();
        #pragma unroll
        for (int k = 0; k < 16; k++) {
            float4 a4 = *(const float4*)&As[k][ty * 4];
            float4 b4 = *(const float4*)&Bs[k][tx * 4];
            float ar[4] = {a4.x, a4.y, a4.z, a4.w};
            float br[4] = {b4.x, b4.y, b4.z, b4.w};
            #pragma unroll
            for (int i = 0; i < 4; i++)
                #pragma unroll
                for (int j = 0; j < 4; j++)
                    acc[i][j] += ar[i] * br[j];
        }
        __syncthreads();
    }

    const int base = d_offs[e];
    #pragma unroll
    for (int i = 0; i < 4; i++) {
        int m = m0 + ty * 4 + i;
        if (m < C) {
            size_t row = (size_t)(base + m) * H + n0 + tx * 4;
            float4 o;
            o.x = fmaxf(acc[i][0] + b1[e * H + n0 + tx * 4 + 0], 0.f);
            o.y = fmaxf(acc[i][1] + b1[e * H + n0 + tx * 4 + 1], 0.f);
            o.z = fmaxf(acc[i][2] + b1[e * H + n0 + tx * 4 + 2], 0.f);
            o.w = fmaxf(acc[i][3] + b1[e * H + n0 + tx * 4 + 3], 0.f);
            *(float4*)&d_h[row] = o;
        }
    }
}

// ---------------- grouped GEMM 2: y = wt * (h @ W2[e] + b2[e]) ----------------
__global__ __launch_bounds__(256) void gemm2_kernel(const float* __restrict__ W2,
                                                    const float* __restrict__ b2) {
    const int e = blockIdx.z;
    const int C = d_counts[e];
    const int m0 = blockIdx.y * 64;
    if (m0 >= C) return;
    const int n0 = blockIdx.x * 64;
    const int base = d_offs[e];

    __shared__ __align__(16) float As[16][64];
    __shared__ __align__(16) float Bs[16][64];

    const int tid = threadIdx.x;
    const int a_row = tid >> 2;
    const int a_col = (tid & 3) << 2;
    const int b_row = tid >> 4;
    const int b_col = (tid & 15) << 2;
    const int ty = tid >> 4;
    const int tx = tid & 15;

    int mi = m0 + a_row;
    int mclamp = (mi < C ? mi : 0);
    const float* arow = d_h + (size_t)(base + mclamp) * H;
    const float* bptr = W2 + (size_t)e * H * O + n0;

    float acc[4][4] = {};

    for (int k0 = 0; k0 < H; k0 += 16) {
        float4 av = *(const float4*)(arow + k0 + a_col);
        float4 bv = *(const float4*)(bptr + (size_t)(k0 + b_row) * O + b_col);
        As[a_col + 0][a_row] = av.x;
        As[a_col + 1][a_row] = av.y;
        As[a_col + 2][a_row] = av.z;
        As[a_col + 3][a_row] = av.w;
        *(float4*)&Bs[b_row][b_col] = bv;
        __syncthreads();
        #pragma unroll
        for (int k = 0; k < 16; k++) {
            float4 a4 = *(const float4*)&As[k][ty * 4];
            float4 b4 = *(const float4*)&Bs[k][tx * 4];
            float ar[4] = {a4.x, a4.y, a4.z, a4.w};
            float br[4] = {b4.x, b4.y, b4.z, b4.w};
            #pragma unroll
            for (int i = 0; i < 4; i++)
                #pragma unroll
                for (int j = 0; j < 4; j++)
                    acc[i][j] += ar[i] * br[j];
        }
        __syncthreads();
    }

    #pragma unroll
    for (int i = 0; i < 4; i++) {
        int m = m0 + ty * 4 + i;
        if (m < C) {
            float wt = d_wt[e * NTOK + m];
            size_t row = (size_t)(base + m) * O + n0 + tx * 4;
            float4 o;
            o.x = wt * (acc[i][0] + b2[e * O + n0 + tx * 4 + 0]);
            o.y = wt * (acc[i][1] + b2[e * O + n0 + tx * 4 + 1]);
            o.z = wt * (acc[i][2] + b2[e * O + n0 + tx * 4 + 2]);
            o.w = wt * (acc[i][3] + b2[e * O + n0 + tx * 4 + 3]);
            *(float4*)&d_y[row] = o;
        }
    }
}

// ---------------- combine: out[n] = y[slot0] + y[slot1] ----------------
__global__ void combine_kernel(float* __restrict__ out) {
    int idx = blockIdx.x * blockDim.x + threadIdx.x;  // over N*O/4
    int n = idx / (O / 4);
    int o4 = (idx % (O / 4)) * 4;
    int s0 = d_slot[n * 2 + 0];
    int s1 = d_slot[n * 2 + 1];
    int c0 = d_offs[s0 >> 12] + (s0 & (NTOK - 1));
    int c1 = d_offs[s1 >> 12] + (s1 & (NTOK - 1));
    float4 a = *(const float4*)&d_y[(size_t)c0 * O + o4];
    float4 b = *(const float4*)&d_y[(size_t)c1 * O + o4];
    float4 r;
    r.x = a.x + b.x; r.y = a.y + b.y; r.z = a.z + b.z; r.w = a.w + b.w;
    *(float4*)&out[(size_t)n * O + o4] = r;
}

extern "C" void kernel_launch(void* const* d_in, const int* in_sizes, int n_in,
                              void* d_out, int out_size) {
    const float* x  = (const float*)d_in[0];
    const float* W1 = (const float*)d_in[1];
    const float* b1 = (const float*)d_in[2];
    const float* W2 = (const float*)d_in[3];
    const float* b2 = (const float*)d_in[4];
    const float* Wg = (const float*)d_in[5];
    const float* bg = (const float*)d_in[6];
    float* out = (float*)d_out;

    zero_counts_kernel<<<1, 32>>>();
    gate_kernel<<<NTOK, 256>>>(x, Wg, bg);
    scan_kernel<<<1, 1>>>();
    gemm1_kernel<<<dim3(H / 64, NTOK / 64, E), 256>>>(x, W1, b1);
    gemm2_kernel<<<dim3(O / 64, NTOK / 64, E), 256>>>(W2, b2);
    combine_kernel<<<(NTOK * O / 4) / 256, 256>>>(out);
}

// round 5
// speedup vs baseline: 1.5301x; 1.5301x over previous
#include <cuda_runtime.h>
#include <cuda_bf16.h>
#include <stdint.h>
#include <math.h>

#define E 8
#define D 1024
#define H 4096
#define O 1024
#define NTOK 4096

// ---------------- scratch ----------------
__device__ int   d_counts[E];
__device__ int   d_offs[E];
__device__ int   d_tok[E * NTOK];
__device__ float d_wt[E * NTOK];
__device__ int   d_slot[NTOK * 2];
__device__ float d_h[(size_t)2 * NTOK * H];   // gathered hidden, f32
__device__ float d_y[(size_t)2 * NTOK * O];   // gathered output, f32

// ---------------- helpers ----------------
__device__ __forceinline__ void mma16816(float* c, const uint32_t* a, const uint32_t* b) {
    asm volatile("mma.sync.aligned.m16n8k16.row.col.f32.bf16.bf16.f32 "
                 "{%0,%1,%2,%3}, {%4,%5,%6,%7}, {%8,%9}, {%0,%1,%2,%3};"
                 : "+f"(c[0]), "+f"(c[1]), "+f"(c[2]), "+f"(c[3])
                 : "r"(a[0]), "r"(a[1]), "r"(a[2]), "r"(a[3]), "r"(b[0]), "r"(b[1]));
}
__device__ __forceinline__ void split2(float x0, float x1, uint32_t& hi, uint32_t& lo) {
    __nv_bfloat16 h0 = __float2bfloat16(x0), h1 = __float2bfloat16(x1);
    float r0 = x0 - __bfloat162float(h0), r1 = x1 - __bfloat162float(h1);
    __nv_bfloat16 l0 = __float2bfloat16(r0), l1 = __float2bfloat16(r1);
    hi = ((uint32_t)__bfloat16_as_ushort(h1) << 16) | __bfloat16_as_ushort(h0);
    lo = ((uint32_t)__bfloat16_as_ushort(l1) << 16) | __bfloat16_as_ushort(l0);
}

// ---------------- routing ----------------
__global__ void zero_counts_kernel() {
    if (threadIdx.x < E) d_counts[threadIdx.x] = 0;
}

__global__ void gate_kernel(const float* __restrict__ x,
                            const float* __restrict__ Wg,
                            const float* __restrict__ bg) {
    int n = blockIdx.x;
    int tid = threadIdx.x;
    int w = tid >> 5;
    int lane = tid & 31;
    const float* xr = x + (size_t)n * D;

    float acc = 0.f;
    for (int d = lane; d < D; d += 32)
        acc += xr[d] * Wg[d * E + w];
    #pragma unroll
    for (int off = 16; off; off >>= 1)
        acc += __shfl_down_sync(0xffffffffu, acc, off);

    __shared__ float logits[E];
    if (lane == 0) logits[w] = acc + bg[w];
    __syncthreads();

    if (tid == 0) {
        int i0 = 0; float v0 = logits[0];
        #pragma unroll
        for (int e = 1; e < E; e++)
            if (logits[e] > v0) { v0 = logits[e]; i0 = e; }
        int i1 = -1; float v1 = -3.0e38f;
        #pragma unroll
        for (int e = 0; e < E; e++)
            if (e != i0 && logits[e] > v1) { v1 = logits[e]; i1 = e; }
        float w0 = 1.f / (1.f + expf(v1 - v0));
        float w1 = 1.f - w0;

        int p0 = atomicAdd(&d_counts[i0], 1);
        d_tok[i0 * NTOK + p0] = n;
        d_wt [i0 * NTOK + p0] = w0;
        d_slot[n * 2 + 0] = i0 * NTOK + p0;

        int p1 = atomicAdd(&d_counts[i1], 1);
        d_tok[i1 * NTOK + p1] = n;
        d_wt [i1 * NTOK + p1] = w1;
        d_slot[n * 2 + 1] = i1 * NTOK + p1;
    }
}

__global__ void scan_kernel() {
    if (threadIdx.x == 0) {
        int t = 0;
        #pragma unroll
        for (int e = 0; e < E; e++) { d_offs[e] = t; t += d_counts[e]; }
    }
}

// ---------------- HMMA grouped GEMM ----------------
// Block tile 128x128x32, 8 warps (2m x 4n), warp tile 64x32, bf16x3 compensated.
// A staged from f32 rows (x or d_h), split inline. B staged DIRECTLY from
// row-major W [K,NOUT]: each thread reads a 4k x 4n float micro-tile and stores
// it transposed+split into sB[n][k]. SMEM rows padded to 40 bf16 (80 B).
#define SROW 40

template <bool FIRST>
__global__ void __launch_bounds__(256)
gemm_hmma(const float* __restrict__ x, const float* __restrict__ W,
          const float* __restrict__ bias) {
    const int e = blockIdx.z;
    const int C = d_counts[e];
    const int m0 = blockIdx.y * 128;
    if (m0 >= C) return;
    const int n0 = blockIdx.x * 128;
    constexpr int K = FIRST ? D : H;
    constexpr int NOUT = FIRST ? H : O;
    const int base = d_offs[e];

    __shared__ __nv_bfloat16 sAh[128][SROW];
    __shared__ __nv_bfloat16 sAl[128][SROW];
    __shared__ __nv_bfloat16 sBh[128][SROW];
    __shared__ __nv_bfloat16 sBl[128][SROW];

    const int tid = threadIdx.x;
    const int lane = tid & 31;
    const int wid = tid >> 5;
    const int warp_m = wid >> 2;     // 0..1
    const int warp_n = wid & 3;      // 0..3
    const int g = lane >> 2;         // 0..7
    const int t = lane & 3;          // 0..3

    // A staging: row lr, k-half hf (16 of 32)
    const int lr = tid >> 1;
    const int hf = tid & 1;
    // B staging: k-quad kq (4 of 32 k's), n-quad nb (4 of 128 n's)
    const int kq = tid >> 5;         // 0..7
    const int nb = tid & 31;         // 0..31

    int mi = m0 + lr; if (mi > C - 1) mi = C - 1;
    const float* arow = FIRST ? (x + (size_t)d_tok[e * NTOK + mi] * D)
                              : (d_h + (size_t)(base + mi) * H);
    const float* wbase = W + (size_t)e * K * NOUT + (size_t)(kq * 4) * NOUT + n0 + nb * 4;

    float acc[4][4][4] = {};

    uint4 rAh0, rAh1, rAl0, rAl1;
    float4 fb[4];

    auto gload = [&](int kb) {
        const float* s = arow + kb + hf * 16;
        float4 f0 = *(const float4*)(s);
        float4 f1 = *(const float4*)(s + 4);
        float4 f2 = *(const float4*)(s + 8);
        float4 f3 = *(const float4*)(s + 12);
        uint32_t h[8], l[8];
        split2(f0.x, f0.y, h[0], l[0]); split2(f0.z, f0.w, h[1], l[1]);
        split2(f1.x, f1.y, h[2], l[2]); split2(f1.z, f1.w, h[3], l[3]);
        split2(f2.x, f2.y, h[4], l[4]); split2(f2.z, f2.w, h[5], l[5]);
        split2(f3.x, f3.y, h[6], l[6]); split2(f3.z, f3.w, h[7], l[7]);
        rAh0 = make_uint4(h[0], h[1], h[2], h[3]);
        rAh1 = make_uint4(h[4], h[5], h[6], h[7]);
        rAl0 = make_uint4(l[0], l[1], l[2], l[3]);
        rAl1 = make_uint4(l[4], l[5], l[6], l[7]);
        const float* wp = wbase + (size_t)kb * NOUT;
        #pragma unroll
        for (int r = 0; r < 4; r++)
            fb[r] = *(const float4*)(wp + (size_t)r * NOUT);
    };

    auto sstore = [&]() {
        *(uint4*)&sAh[lr][hf * 16]     = rAh0;
        *(uint4*)&sAh[lr][hf * 16 + 8] = rAh1;
        *(uint4*)&sAl[lr][hf * 16]     = rAl0;
        *(uint4*)&sAl[lr][hf * 16 + 8] = rAl1;
        float v[4][4] = {
            {fb[0].x, fb[0].y, fb[0].z, fb[0].w},
            {fb[1].x, fb[1].y, fb[1].z, fb[1].w},
            {fb[2].x, fb[2].y, fb[2].z, fb[2].w},
            {fb[3].x, fb[3].y, fb[3].z, fb[3].w}};
        #pragma unroll
        for (int j = 0; j < 4; j++) {   // n within quad
            uint32_t h0, l0, h1, l1;
            split2(v[0][j], v[1][j], h0, l0);   // k pair (0,1)
            split2(v[2][j], v[3][j], h1, l1);   // k pair (2,3)
            *(uint2*)&sBh[nb * 4 + j][kq * 4] = make_uint2(h0, h1);
            *(uint2*)&sBl[nb * 4 + j][kq * 4] = make_uint2(l0, l1);
        }
    };

    auto compute = [&]() {
        #pragma unroll
        for (int kh = 0; kh < 2; kh++) {
            const int kc = kh * 16 + 2 * t;   // fragment k base
            uint32_t bh[4][2], bl[4][2];
            #pragma unroll
            for (int nt = 0; nt < 4; nt++) {
                const int br = warp_n * 32 + nt * 8 + g;
                bh[nt][0] = *(const uint32_t*)&sBh[br][kc];
                bh[nt][1] = *(const uint32_t*)&sBh[br][kc + 8];
                bl[nt][0] = *(const uint32_t*)&sBl[br][kc];
                bl[nt][1] = *(const uint32_t*)&sBl[br][kc + 8];
            }
            #pragma unroll
            for (int mt = 0; mt < 4; mt++) {
                const int ar = warp_m * 64 + mt * 16 + g;
                uint32_t ah[4], al[4];
                ah[0] = *(const uint32_t*)&sAh[ar][kc];
                ah[1] = *(const uint32_t*)&sAh[ar + 8][kc];
                ah[2] = *(const uint32_t*)&sAh[ar][kc + 8];
                ah[3] = *(const uint32_t*)&sAh[ar + 8][kc + 8];
                al[0] = *(const uint32_t*)&sAl[ar][kc];
                al[1] = *(const uint32_t*)&sAl[ar + 8][kc];
                al[2] = *(const uint32_t*)&sAl[ar][kc + 8];
                al[3] = *(const uint32_t*)&sAl[ar + 8][kc + 8];
                #pragma unroll
                for (int nt = 0; nt < 4; nt++) {
                    mma16816(acc[mt][nt], ah, bh[nt]);
                    mma16816(acc[mt][nt], al, bh[nt]);
                    mma16816(acc[mt][nt], ah, bl[nt]);
                }
            }
        }
    };

    const int NCH = K / 32;
    gload(0);
    for (int c = 0; c < NCH; c++) {
        __syncthreads();                       // prior compute done reading smem
        sstore();
        if (c + 1 < NCH) gload((c + 1) * 32);  // LDGs in flight under compute
        __syncthreads();                       // staged data visible
        compute();
    }

    // ---------------- epilogue ----------------
    #pragma unroll
    for (int mt = 0; mt < 4; mt++) {
        const int rw = warp_m * 64 + mt * 16 + g;
        #pragma unroll
        for (int hrow = 0; hrow < 2; hrow++) {
            const int m = m0 + rw + hrow * 8;
            if (m >= C) continue;
            #pragma unroll
            for (int nt = 0; nt < 4; nt++) {
                const int col = n0 + warp_n * 32 + nt * 8 + 2 * t;
                float v0 = acc[mt][nt][hrow * 2 + 0] + bias[e * NOUT + col];
                float v1 = acc[mt][nt][hrow * 2 + 1] + bias[e * NOUT + col + 1];
                if (FIRST) {
                    float2 o;
                    o.x = fmaxf(v0, 0.f);
                    o.y = fmaxf(v1, 0.f);
                    *(float2*)(d_h + (size_t)(base + m) * H + col) = o;
                } else {
                    float wt = d_wt[e * NTOK + m];
                    float2 o;
                    o.x = wt * v0;
                    o.y = wt * v1;
                    *(float2*)(d_y + (size_t)(base + m) * O + col) = o;
                }
            }
        }
    }
}

// ---------------- combine ----------------
__global__ void combine_kernel(float* __restrict__ out) {
    int idx = blockIdx.x * blockDim.x + threadIdx.x;
    int n = idx / (O / 4);
    int o4 = (idx % (O / 4)) * 4;
    int s0 = d_slot[n * 2 + 0];
    int s1 = d_slot[n * 2 + 1];
    int c0 = d_offs[s0 >> 12] + (s0 & (NTOK - 1));
    int c1 = d_offs[s1 >> 12] + (s1 & (NTOK - 1));
    float4 a = *(const float4*)&d_y[(size_t)c0 * O + o4];
    float4 b = *(const float4*)&d_y[(size_t)c1 * O + o4];
    float4 r;
    r.x = a.x + b.x; r.y = a.y + b.y; r.z = a.z + b.z; r.w = a.w + b.w;
    *(float4*)&out[(size_t)n * O + o4] = r;
}

extern "C" void kernel_launch(void* const* d_in, const int* in_sizes, int n_in,
                              void* d_out, int out_size) {
    const float* x  = (const float*)d_in[0];
    const float* W1 = (const float*)d_in[1];
    const float* b1 = (const float*)d_in[2];
    const float* W2 = (const float*)d_in[3];
    const float* b2 = (const float*)d_in[4];
    const float* Wg = (const float*)d_in[5];
    const float* bg = (const float*)d_in[6];
    float* out = (float*)d_out;

    zero_counts_kernel<<<1, 32>>>();
    gate_kernel<<<NTOK, 256>>>(x, Wg, bg);
    scan_kernel<<<1, 1>>>();

    gemm_hmma<true ><<<dim3(H / 128, NTOK / 128, E), 256>>>(x, W1, b1);
    gemm_hmma<false><<<dim3(O / 128, NTOK / 128, E), 256>>>(nullptr, W2, b2);

    combine_kernel<<<(NTOK * O / 4) / 256, 256>>>(out);
}

// round 6
// speedup vs baseline: 1.6350x; 1.0686x over previous
#include <cuda_runtime.h>
#include <cuda_bf16.h>
#include <stdint.h>
#include <math.h>

#define E 8
#define D 1024
#define H 4096
#define O 1024
#define NTOK 4096

// ---------------- scratch ----------------
__device__ int   d_counts[E];
__device__ int   d_offs[E];
__device__ int   d_tok[E * NTOK];
__device__ float d_wt[E * NTOK];
__device__ int   d_slot[NTOK * 2];
__device__ float d_h[(size_t)2 * NTOK * H];   // gathered hidden, f32
__device__ float d_y[(size_t)2 * NTOK * O];   // gathered output, f32

// ---------------- helpers ----------------
__device__ __forceinline__ uint32_t smem_u32(const void* p) {
    uint32_t a;
    asm("{ .reg .u64 t; cvta.to.shared.u64 t, %1; cvt.u32.u64 %0, t; }" : "=r"(a) : "l"(p));
    return a;
}
__device__ __forceinline__ void ldm_x4(uint32_t* d, uint32_t a) {
    asm volatile("ldmatrix.sync.aligned.m8n8.x4.shared.b16 {%0,%1,%2,%3}, [%4];"
                 : "=r"(d[0]), "=r"(d[1]), "=r"(d[2]), "=r"(d[3]) : "r"(a));
}
__device__ __forceinline__ void mma16816(float* c, const uint32_t* a, const uint32_t* b) {
    asm volatile("mma.sync.aligned.m16n8k16.row.col.f32.bf16.bf16.f32 "
                 "{%0,%1,%2,%3}, {%4,%5,%6,%7}, {%8,%9}, {%0,%1,%2,%3};"
                 : "+f"(c[0]), "+f"(c[1]), "+f"(c[2]), "+f"(c[3])
                 : "r"(a[0]), "r"(a[1]), "r"(a[2]), "r"(a[3]), "r"(b[0]), "r"(b[1]));
}
__device__ __forceinline__ void split2(float x0, float x1, uint32_t& hi, uint32_t& lo) {
    __nv_bfloat16 h0 = __float2bfloat16(x0), h1 = __float2bfloat16(x1);
    float r0 = x0 - __bfloat162float(h0), r1 = x1 - __bfloat162float(h1);
    __nv_bfloat16 l0 = __float2bfloat16(r0), l1 = __float2bfloat16(r1);
    hi = ((uint32_t)__bfloat16_as_ushort(h1) << 16) | __bfloat16_as_ushort(h0);
    lo = ((uint32_t)__bfloat16_as_ushort(l1) << 16) | __bfloat16_as_ushort(l0);
}

// ---------------- routing ----------------
__global__ void zero_counts_kernel() {
    if (threadIdx.x < E) d_counts[threadIdx.x] = 0;
}

__global__ void gate_kernel(const float* __restrict__ x,
                            const float* __restrict__ Wg,
                            const float* __restrict__ bg) {
    int n = blockIdx.x;
    int tid = threadIdx.x;
    int w = tid >> 5;
    int lane = tid & 31;
    const float* xr = x + (size_t)n * D;

    float acc = 0.f;
    for (int d = lane; d < D; d += 32)
        acc += xr[d] * Wg[d * E + w];
    #pragma unroll
    for (int off = 16; off; off >>= 1)
        acc += __shfl_down_sync(0xffffffffu, acc, off);

    __shared__ float logits[E];
    if (lane == 0) logits[w] = acc + bg[w];
    __syncthreads();

    if (tid == 0) {
        int i0 = 0; float v0 = logits[0];
        #pragma unroll
        for (int e = 1; e < E; e++)
            if (logits[e] > v0) { v0 = logits[e]; i0 = e; }
        int i1 = -1; float v1 = -3.0e38f;
        #pragma unroll
        for (int e = 0; e < E; e++)
            if (e != i0 && logits[e] > v1) { v1 = logits[e]; i1 = e; }
        float w0 = 1.f / (1.f + expf(v1 - v0));
        float w1 = 1.f - w0;

        int p0 = atomicAdd(&d_counts[i0], 1);
        d_tok[i0 * NTOK + p0] = n;
        d_wt [i0 * NTOK + p0] = w0;
        d_slot[n * 2 + 0] = i0 * NTOK + p0;

        int p1 = atomicAdd(&d_counts[i1], 1);
        d_tok[i1 * NTOK + p1] = n;
        d_wt [i1 * NTOK + p1] = w1;
        d_slot[n * 2 + 1] = i1 * NTOK + p1;
    }
}

__global__ void scan_kernel() {
    if (threadIdx.x == 0) {
        int t = 0;
        #pragma unroll
        for (int e = 0; e < E; e++) { d_offs[e] = t; t += d_counts[e]; }
    }
}

// ---------------- HMMA grouped GEMM ----------------
// Block tile 128x128x32, 8 warps (2m x 4n), warp tile 64x32, bf16x3 compensated.
// Double-buffered dynamic SMEM, ldmatrix fragment loads, one sync per chunk.
#define SROW 40
#define TILE_BYTES (128 * SROW * 2)          // 10240
#define STAGE_BYTES (4 * TILE_BYTES)         // Ah|Al|Bh|Bl = 40960
#define OFF_AH 0
#define OFF_AL TILE_BYTES
#define OFF_BH (2 * TILE_BYTES)
#define OFF_BL (3 * TILE_BYTES)

template <bool FIRST>
__global__ void __launch_bounds__(256)
gemm_hmma(const float* __restrict__ x, const float* __restrict__ W,
          const float* __restrict__ bias) {
    const int e = blockIdx.z;
    const int C = d_counts[e];
    const int m0 = blockIdx.y * 128;
    if (m0 >= C) return;
    const int n0 = blockIdx.x * 128;
    constexpr int K = FIRST ? D : H;
    constexpr int NOUT = FIRST ? H : O;
    const int base = d_offs[e];

    extern __shared__ __align__(16) char smem[];
    const uint32_t sb = smem_u32(smem);

    const int tid = threadIdx.x;
    const int lane = tid & 31;
    const int wid = tid >> 5;
    const int warp_m = wid >> 2;     // 0..1
    const int warp_n = wid & 3;      // 0..3
    const int g = lane >> 2;         // 0..7
    const int t = lane & 3;          // 0..3

    // A staging: row lr, k-half hf (16 of 32)
    const int lr = tid >> 1;
    const int hf = tid & 1;
    // B staging: k-quad kq (k=kq*4), n-quad nq (n=nq*4)
    const int kq = tid & 7;
    const int nq = tid >> 3;         // 0..31

    int mi = m0 + lr; if (mi > C - 1) mi = C - 1;
    const float* arow = FIRST ? (x + (size_t)d_tok[e * NTOK + mi] * D)
                              : (d_h + (size_t)(base + mi) * H);
    const float* wbase = W + (size_t)e * K * NOUT + (size_t)(kq * 4) * NOUT + n0 + nq * 4;

    float acc[4][4][4] = {};

    uint4 rAh0, rAh1, rAl0, rAl1;
    float4 fb[4];

    auto gload = [&](int kb) {
        const float* s = arow + kb + hf * 16;
        float4 f0 = *(const float4*)(s);
        float4 f1 = *(const float4*)(s + 4);
        float4 f2 = *(const float4*)(s + 8);
        float4 f3 = *(const float4*)(s + 12);
        uint32_t h[8], l[8];
        split2(f0.x, f0.y, h[0], l[0]); split2(f0.z, f0.w, h[1], l[1]);
        split2(f1.x, f1.y, h[2], l[2]); split2(f1.z, f1.w, h[3], l[3]);
        split2(f2.x, f2.y, h[4], l[4]); split2(f2.z, f2.w, h[5], l[5]);
        split2(f3.x, f3.y, h[6], l[6]); split2(f3.z, f3.w, h[7], l[7]);
        rAh0 = make_uint4(h[0], h[1], h[2], h[3]);
        rAh1 = make_uint4(h[4], h[5], h[6], h[7]);
        rAl0 = make_uint4(l[0], l[1], l[2], l[3]);
        rAl1 = make_uint4(l[4], l[5], l[6], l[7]);
        const float* wp = wbase + (size_t)kb * NOUT;
        #pragma unroll
        for (int r = 0; r < 4; r++)
            fb[r] = *(const float4*)(wp + (size_t)r * NOUT);
    };

    auto sstore = [&](int st) {
        char* sbp = smem + st * STAGE_BYTES;
        __nv_bfloat16* pAh = (__nv_bfloat16*)(sbp + OFF_AH);
        __nv_bfloat16* pAl = (__nv_bfloat16*)(sbp + OFF_AL);
        __nv_bfloat16* pBh = (__nv_bfloat16*)(sbp + OFF_BH);
        __nv_bfloat16* pBl = (__nv_bfloat16*)(sbp + OFF_BL);
        *(uint4*)(pAh + lr * SROW + hf * 16)     = rAh0;
        *(uint4*)(pAh + lr * SROW + hf * 16 + 8) = rAh1;
        *(uint4*)(pAl + lr * SROW + hf * 16)     = rAl0;
        *(uint4*)(pAl + lr * SROW + hf * 16 + 8) = rAl1;
        float v[4][4] = {
            {fb[0].x, fb[0].y, fb[0].z, fb[0].w},
            {fb[1].x, fb[1].y, fb[1].z, fb[1].w},
            {fb[2].x, fb[2].y, fb[2].z, fb[2].w},
            {fb[3].x, fb[3].y, fb[3].z, fb[3].w}};
        #pragma unroll
        for (int j = 0; j < 4; j++) {   // n within quad
            uint32_t h0, l0, h1, l1;
            split2(v[0][j], v[1][j], h0, l0);   // k pair (0,1)
            split2(v[2][j], v[3][j], h1, l1);   // k pair (2,3)
            *(uint2*)(pBh + (nq * 4 + j) * SROW + kq * 4) = make_uint2(h0, h1);
            *(uint2*)(pBl + (nq * 4 + j) * SROW + kq * 4) = make_uint2(l0, l1);
        }
    };

    // ldmatrix addressing
    const uint32_t a_lane_off = (uint32_t)((lane & 15) * (SROW * 2) + (lane >> 4) * 16);
    const uint32_t b_lane_off = (uint32_t)(((lane & 7) + (lane >> 4) * 8) * (SROW * 2)
                                           + ((lane >> 3) & 1) * 16);

    auto compute = [&](int st) {
        uint32_t s0 = sb + (uint32_t)(st * STAGE_BYTES);
        uint32_t aAh = s0 + OFF_AH + a_lane_off + (uint32_t)(warp_m * 64 * SROW * 2);
        uint32_t aAl = s0 + OFF_AL + a_lane_off + (uint32_t)(warp_m * 64 * SROW * 2);
        uint32_t aBh = s0 + OFF_BH + b_lane_off + (uint32_t)(warp_n * 32 * SROW * 2);
        uint32_t aBl = s0 + OFF_BL + b_lane_off + (uint32_t)(warp_n * 32 * SROW * 2);
        #pragma unroll
        for (int kh = 0; kh < 2; kh++) {
            const uint32_t kb = kh * 32;
            uint32_t bh[2][4], bl[2][4];       // [pair][4 regs = 2 n-tiles]
            #pragma unroll
            for (int p = 0; p < 2; p++) {
                ldm_x4(bh[p], aBh + kb + (uint32_t)(p * 16 * SROW * 2));
                ldm_x4(bl[p], aBl + kb + (uint32_t)(p * 16 * SROW * 2));
            }
            #pragma unroll
            for (int mt = 0; mt < 4; mt++) {
                uint32_t ah[4], al[4];
                ldm_x4(ah, aAh + kb + (uint32_t)(mt * 16 * SROW * 2));
                ldm_x4(al, aAl + kb + (uint32_t)(mt * 16 * SROW * 2));
                #pragma unroll
                for (int nt = 0; nt < 4; nt++) {
                    const uint32_t* bhf = &bh[nt >> 1][(nt & 1) * 2];
                    const uint32_t* blf = &bl[nt >> 1][(nt & 1) * 2];
                    mma16816(acc[mt][nt], ah, bhf);
                    mma16816(acc[mt][nt], al, bhf);
                    mma16816(acc[mt][nt], ah, blf);
                }
            }
        }
    };

    const int NCH = K / 32;
    gload(0);
    sstore(0);
    __syncthreads();
    for (int c = 0; c < NCH; c++) {
        if (c + 1 < NCH) gload((c + 1) * 32);
        compute(c & 1);
        if (c + 1 < NCH) sstore((c + 1) & 1);
        __syncthreads();
    }

    // ---------------- epilogue ----------------
    #pragma unroll
    for (int mt = 0; mt < 4; mt++) {
        const int rw = warp_m * 64 + mt * 16 + g;
        #pragma unroll
        for (int hrow = 0; hrow < 2; hrow++) {
            const int m = m0 + rw + hrow * 8;
            if (m >= C) continue;
            #pragma unroll
            for (int nt = 0; nt < 4; nt++) {
                const int col = n0 + warp_n * 32 + nt * 8 + 2 * t;
                float v0 = acc[mt][nt][hrow * 2 + 0] + bias[e * NOUT + col];
                float v1 = acc[mt][nt][hrow * 2 + 1] + bias[e * NOUT + col + 1];
                if (FIRST) {
                    float2 o;
                    o.x = fmaxf(v0, 0.f);
                    o.y = fmaxf(v1, 0.f);
                    *(float2*)(d_h + (size_t)(base + m) * H + col) = o;
                } else {
                    float wt = d_wt[e * NTOK + m];
                    float2 o;
                    o.x = wt * v0;
                    o.y = wt * v1;
                    *(float2*)(d_y + (size_t)(base + m) * O + col) = o;
                }
            }
        }
    }
}

// ---------------- combine ----------------
__global__ void combine_kernel(float* __restrict__ out) {
    int idx = blockIdx.x * blockDim.x + threadIdx.x;
    int n = idx / (O / 4);
    int o4 = (idx % (O / 4)) * 4;
    int s0 = d_slot[n * 2 + 0];
    int s1 = d_slot[n * 2 + 1];
    int c0 = d_offs[s0 >> 12] + (s0 & (NTOK - 1));
    int c1 = d_offs[s1 >> 12] + (s1 & (NTOK - 1));
    float4 a = *(const float4*)&d_y[(size_t)c0 * O + o4];
    float4 b = *(const float4*)&d_y[(size_t)c1 * O + o4];
    float4 r;
    r.x = a.x + b.x; r.y = a.y + b.y; r.z = a.z + b.z; r.w = a.w + b.w;
    *(float4*)&out[(size_t)n * O + o4] = r;
}

extern "C" void kernel_launch(void* const* d_in, const int* in_sizes, int n_in,
                              void* d_out, int out_size) {
    const float* x  = (const float*)d_in[0];
    const float* W1 = (const float*)d_in[1];
    const float* b1 = (const float*)d_in[2];
    const float* W2 = (const float*)d_in[3];
    const float* b2 = (const float*)d_in[4];
    const float* Wg = (const float*)d_in[5];
    const float* bg = (const float*)d_in[6];
    float* out = (float*)d_out;

    cudaFuncSetAttribute(gemm_hmma<true>,  cudaFuncAttributeMaxDynamicSharedMemorySize, 2 * STAGE_BYTES);
    cudaFuncSetAttribute(gemm_hmma<false>, cudaFuncAttributeMaxDynamicSharedMemorySize, 2 * STAGE_BYTES);

    zero_counts_kernel<<<1, 32>>>();
    gate_kernel<<<NTOK, 256>>>(x, Wg, bg);
    scan_kernel<<<1, 1>>>();

    gemm_hmma<true ><<<dim3(H / 128, NTOK / 128, E), 256, 2 * STAGE_BYTES>>>(x, W1, b1);
    gemm_hmma<false><<<dim3(O / 128, NTOK / 128, E), 256, 2 * STAGE_BYTES>>>(nullptr, W2, b2);

    combine_kernel<<<(NTOK * O / 4) / 256, 256>>>(out);
}